// round 11
// baseline (speedup 1.0000x reference)
#include <cuda_runtime.h>

#define NB   32
#define CCH  192
#define HW   112
#define IMG  (HW*HW)
#define TILE_H 16
#define TILES  (HW / TILE_H)   // 7
#define NHW_F  ((float)(NB*IMG))
#define BN_EPS 1e-5f

// Scratch (no cudaMalloc allowed): per-(c,n) partial sums (channel-major) + affine.
__device__ float g_p1[CCH * NB];        // sum of raw conv (no bias)
__device__ float g_p2[CCH * NB];        // sum of raw conv^2
__device__ float g_scale[CCH];
__device__ float g_shift[CCH];
__device__ unsigned int g_cnt[CCH];     // zero-init; reset to 0 by last block each run

// Load 6 input rows (h-1 .. h+4) as float4 per lane; lanes >=28 and OOB rows get 0.
__device__ __forceinline__ void load_rows(const float* __restrict__ base,
                                          int h, int lane, bool active,
                                          float4* v) {
    #pragma unroll
    for (int r = 0; r < 6; r++) {
        int row = h - 1 + r;
        float4 t = make_float4(0.f, 0.f, 0.f, 0.f);
        if (active && (unsigned)row < HW)
            t = __ldg(reinterpret_cast<const float4*>(base + row * HW) + lane);
        v[r] = t;
    }
}

// Scalar conv 4x4 micro-tile (proven fastest form).
// NOTE: lanes >= 28 produce garbage (their left halo shuffles in lane 27's real
// data) — callers MUST mask them out of any reduction/store.
__device__ __forceinline__ void conv44(const float4* v, const float* __restrict__ k,
                                       int lane, float acc[4][4]) {
    #pragma unroll
    for (int j = 0; j < 4; j++)
        #pragma unroll
        for (int i = 0; i < 4; i++)
            acc[j][i] = 0.f;

    #pragma unroll
    for (int r = 0; r < 6; r++) {
        float left  = __shfl_up_sync(0xFFFFFFFFu, v[r].w, 1);
        float right = __shfl_down_sync(0xFFFFFFFFu, v[r].x, 1);
        if (lane == 0) left = 0.f;
        float p[6] = { left, v[r].x, v[r].y, v[r].z, v[r].w, right };
        #pragma unroll
        for (int j = 0; j < 4; j++) {
            if (j >= r - 2 && j <= r) {
                const float k0 = k[3 * (r - j) + 0];
                const float k1 = k[3 * (r - j) + 1];
                const float k2 = k[3 * (r - j) + 2];
                #pragma unroll
                for (int i = 0; i < 4; i++)
                    acc[j][i] += k0 * p[i] + k1 * p[i + 1] + k2 * p[i + 2];
            }
        }
    }
}

// Pass 1: per-(c,n) sums of conv and conv^2, with fused finalize:
// the last block to finish a channel reduces its 32 partials and writes
// scale/shift (then resets the counter for the next graph replay).
__global__ void __launch_bounds__(224, 8)
stats_kernel(const float* __restrict__ in, const float* __restrict__ w,
             const float* __restrict__ b, const float* __restrict__ gamma,
             const float* __restrict__ beta) {
    __shared__ float red1[7], red2[7];
    __shared__ int s_last;
    int lane = threadIdx.x & 31, wid = threadIdx.x >> 5;
    int c = blockIdx.x, n = blockIdx.y;
    bool active = lane < 28;
    const float* base = in + (size_t)(n * CCH + c) * IMG;

    float k[9];
    #pragma unroll
    for (int i = 0; i < 9; i++) k[i] = __ldg(w + c * 9 + i);

    float s1 = 0.f, s2 = 0.f;
    #pragma unroll
    for (int chunk = 0; chunk < 4; chunk++) {
        int h = wid * TILE_H + chunk * 4;
        float4 v[6];
        load_rows(base, h, lane, active, v);
        float acc[4][4];
        conv44(v, k, lane, acc);
        if (active) {   // REQUIRED: lanes 28-31 hold garbage (see conv44 note)
            #pragma unroll
            for (int j = 0; j < 4; j++)
                #pragma unroll
                for (int i = 0; i < 4; i++) {
                    s1 += acc[j][i];
                    s2 += acc[j][i] * acc[j][i];
                }
        }
    }

    #pragma unroll
    for (int off = 16; off > 0; off >>= 1) {
        s1 += __shfl_down_sync(0xFFFFFFFFu, s1, off);
        s2 += __shfl_down_sync(0xFFFFFFFFu, s2, off);
    }
    if (lane == 0) { red1[wid] = s1; red2[wid] = s2; }
    __syncthreads();
    if (threadIdx.x == 0) {
        float t1 = 0.f, t2 = 0.f;
        #pragma unroll
        for (int i = 0; i < 7; i++) { t1 += red1[i]; t2 += red2[i]; }
        g_p1[c * NB + n] = t1;
        g_p2[c * NB + n] = t2;
        __threadfence();                                // release partials
        unsigned prev = atomicAdd(&g_cnt[c], 1u);
        s_last = (prev == NB - 1);
    }
    __syncthreads();

    // Last block for this channel: reduce 32 partials -> scale/shift.
    if (s_last && wid == 0) {
        __threadfence();                                // acquire partials
        float p1 = g_p1[c * NB + lane];
        float p2 = g_p2[c * NB + lane];
        #pragma unroll
        for (int off = 16; off > 0; off >>= 1) {
            p1 += __shfl_down_sync(0xFFFFFFFFu, p1, off);
            p2 += __shfl_down_sync(0xFFFFFFFFu, p2, off);
        }
        if (lane == 0) {
            float bias  = __ldg(b + c);
            float sum_y = p1 + NHW_F * bias;
            float ssq_y = p2 + 2.f * bias * p1 + NHW_F * bias * bias;
            float mean  = sum_y / NHW_F;
            float var   = ssq_y / NHW_F - mean * mean;
            float sc    = __ldg(gamma + c) * rsqrtf(var + BN_EPS);
            g_scale[c] = sc;
            g_shift[c] = __ldg(beta + c) + sc * (bias - mean);
            g_cnt[c] = 0;                               // rearm for next replay
        }
    }
}

// Pass 2 (proven, 86us): recompute conv, folded scale/shift + ReLU6, plain float4 stores.
__global__ void __launch_bounds__(128)
output_kernel(const float* __restrict__ in,
              const float* __restrict__ w,
              float* __restrict__ out) {
    int lane = threadIdx.x & 31;
    int wid  = threadIdx.x >> 5;
    int c = blockIdx.y, n = blockIdx.z;
    int h = blockIdx.x * TILE_H + wid * 4;
    bool active = lane < 28;

    const float* base = in + (size_t)(n * CCH + c) * IMG;
    float k[9];
    #pragma unroll
    for (int i = 0; i < 9; i++) k[i] = __ldg(w + c * 9 + i);
    float sc = g_scale[c];
    float sh = g_shift[c];

    float4 v[6];
    load_rows(base, h, lane, active, v);

    float acc[4][4];
    conv44(v, k, lane, acc);

    if (active) {
        float* ob = out + (size_t)(n * CCH + c) * IMG + h * HW + lane * 4;
        #pragma unroll
        for (int j = 0; j < 4; j++) {
            float4 o;
            o.x = fminf(fmaxf(fmaf(acc[j][0], sc, sh), 0.f), 6.f);
            o.y = fminf(fmaxf(fmaf(acc[j][1], sc, sh), 0.f), 6.f);
            o.z = fminf(fmaxf(fmaf(acc[j][2], sc, sh), 0.f), 6.f);
            o.w = fminf(fmaxf(fmaf(acc[j][3], sc, sh), 0.f), 6.f);
            *reinterpret_cast<float4*>(ob + j * HW) = o;
        }
    }
}

extern "C" void kernel_launch(void* const* d_in, const int* in_sizes, int n_in,
                              void* d_out, int out_size) {
    const float* in    = (const float*)d_in[0];
    const float* w     = (const float*)d_in[1];
    const float* b     = (const float*)d_in[2];
    const float* gamma = (const float*)d_in[3];
    const float* beta  = (const float*)d_in[4];
    float* out = (float*)d_out;

    dim3 sgrid(CCH, NB);            // 6144 blocks, 224 threads
    dim3 ogrid(TILES, CCH, NB);     // 43008 blocks, 128 threads
    stats_kernel<<<sgrid, 224>>>(in, w, b, gamma, beta);
    output_kernel<<<ogrid, 128>>>(in, w, out);
}

// round 12
// speedup vs baseline: 1.0413x; 1.0413x over previous
#include <cuda_runtime.h>

#define NB   32
#define CCH  192
#define HW   112
#define IMG  (HW*HW)
#define TILE_H 16
#define TILES  (HW / TILE_H)   // 7
#define NHW_F  ((float)(NB*IMG))
#define BN_EPS 1e-5f

// Scratch (no cudaMalloc allowed): per-(c,n) partial sums (channel-major) + affine.
__device__ float g_p1[CCH * NB];   // sum of raw conv (no bias)
__device__ float g_p2[CCH * NB];   // sum of raw conv^2
__device__ float g_scale[CCH];
__device__ float g_shift[CCH];

// Load 6 input rows (h-1 .. h+4) as float4 per lane; lanes >=28 and OOB rows get 0.
__device__ __forceinline__ void load_rows(const float* __restrict__ base,
                                          int h, int lane, bool active,
                                          float4* v) {
    #pragma unroll
    for (int r = 0; r < 6; r++) {
        int row = h - 1 + r;
        float4 t = make_float4(0.f, 0.f, 0.f, 0.f);
        if (active && (unsigned)row < HW)
            t = __ldg(reinterpret_cast<const float4*>(base + row * HW) + lane);
        v[r] = t;
    }
}

// Scalar conv 4x4 micro-tile (proven fastest form).
// NOTE: lanes >= 28 produce garbage (their left halo shuffles in lane 27's real
// data) — callers MUST mask them out of any reduction/store.
__device__ __forceinline__ void conv44(const float4* v, const float* __restrict__ k,
                                       int lane, float acc[4][4]) {
    #pragma unroll
    for (int j = 0; j < 4; j++)
        #pragma unroll
        for (int i = 0; i < 4; i++)
            acc[j][i] = 0.f;

    #pragma unroll
    for (int r = 0; r < 6; r++) {
        float left  = __shfl_up_sync(0xFFFFFFFFu, v[r].w, 1);
        float right = __shfl_down_sync(0xFFFFFFFFu, v[r].x, 1);
        if (lane == 0) left = 0.f;
        float p[6] = { left, v[r].x, v[r].y, v[r].z, v[r].w, right };
        #pragma unroll
        for (int j = 0; j < 4; j++) {
            if (j >= r - 2 && j <= r) {
                const float k0 = k[3 * (r - j) + 0];
                const float k1 = k[3 * (r - j) + 1];
                const float k2 = k[3 * (r - j) + 2];
                #pragma unroll
                for (int i = 0; i < 4; i++)
                    acc[j][i] += k0 * p[i] + k1 * p[i + 1] + k2 * p[i + 2];
            }
        }
    }
}

// Pass 1 (R10-proven, ~61us): per-(c,n) sums of conv and conv^2.
__global__ void __launch_bounds__(224)
stats_kernel(const float* __restrict__ in, const float* __restrict__ w) {
    __shared__ float red1[7], red2[7];
    int lane = threadIdx.x & 31, wid = threadIdx.x >> 5;
    int c = blockIdx.x, n = blockIdx.y;
    bool active = lane < 28;
    const float* base = in + (size_t)(n * CCH + c) * IMG;

    float k[9];
    #pragma unroll
    for (int i = 0; i < 9; i++) k[i] = __ldg(w + c * 9 + i);

    float s1 = 0.f, s2 = 0.f;
    #pragma unroll
    for (int chunk = 0; chunk < 4; chunk++) {
        int h = wid * TILE_H + chunk * 4;
        float4 v[6];
        load_rows(base, h, lane, active, v);
        float acc[4][4];
        conv44(v, k, lane, acc);
        if (active) {   // REQUIRED: lanes 28-31 hold garbage (see conv44 note)
            #pragma unroll
            for (int j = 0; j < 4; j++)
                #pragma unroll
                for (int i = 0; i < 4; i++) {
                    s1 += acc[j][i];
                    s2 += acc[j][i] * acc[j][i];
                }
        }
    }

    #pragma unroll
    for (int off = 16; off > 0; off >>= 1) {
        s1 += __shfl_down_sync(0xFFFFFFFFu, s1, off);
        s2 += __shfl_down_sync(0xFFFFFFFFu, s2, off);
    }
    if (lane == 0) { red1[wid] = s1; red2[wid] = s2; }
    __syncthreads();
    if (threadIdx.x == 0) {
        float t1 = 0.f, t2 = 0.f;
        #pragma unroll
        for (int i = 0; i < 7; i++) { t1 += red1[i]; t2 += red2[i]; }
        g_p1[c * NB + n] = t1;      // channel-major: finalize reads coalesced
        g_p2[c * NB + n] = t2;
    }
}

// Parallel finalize (R10-proven): one warp per channel. PDL: launched while
// stats drains; sync before reading partials.
__global__ void finalize_kernel(const float* __restrict__ b,
                                const float* __restrict__ gamma,
                                const float* __restrict__ beta) {
    cudaGridDependencySynchronize();   // wait for stats partials
    int c = blockIdx.x;
    int lane = threadIdx.x;
    float p1 = g_p1[c * NB + lane];
    float p2 = g_p2[c * NB + lane];
    #pragma unroll
    for (int off = 16; off > 0; off >>= 1) {
        p1 += __shfl_down_sync(0xFFFFFFFFu, p1, off);
        p2 += __shfl_down_sync(0xFFFFFFFFu, p2, off);
    }
    if (lane == 0) {
        float bias  = __ldg(b + c);
        float sum_y = p1 + NHW_F * bias;
        float ssq_y = p2 + 2.f * bias * p1 + NHW_F * bias * bias;
        float mean  = sum_y / NHW_F;
        float var   = ssq_y / NHW_F - mean * mean;
        float sc    = __ldg(gamma + c) * rsqrtf(var + BN_EPS);
        g_scale[c] = sc;
        g_shift[c] = __ldg(beta + c) + sc * (bias - mean);
    }
}

// Pass 2 (R3-proven compute): conv first (independent of finalize), then PDL
// sync, then read folded scale/shift, ReLU6, plain float4 stores.
__global__ void __launch_bounds__(128)
output_kernel(const float* __restrict__ in,
              const float* __restrict__ w,
              float* __restrict__ out) {
    int lane = threadIdx.x & 31;
    int wid  = threadIdx.x >> 5;
    int c = blockIdx.y, n = blockIdx.z;
    int h = blockIdx.x * TILE_H + wid * 4;
    bool active = lane < 28;

    const float* base = in + (size_t)(n * CCH + c) * IMG;
    float k[9];
    #pragma unroll
    for (int i = 0; i < 9; i++) k[i] = __ldg(w + c * 9 + i);

    float4 v[6];
    load_rows(base, h, lane, active, v);

    float acc[4][4];
    conv44(v, k, lane, acc);

    cudaGridDependencySynchronize();   // finalize results ready past this point
    float sc = g_scale[c];
    float sh = g_shift[c];

    if (active) {
        float* ob = out + (size_t)(n * CCH + c) * IMG + h * HW + lane * 4;
        #pragma unroll
        for (int j = 0; j < 4; j++) {
            float4 o;
            o.x = fminf(fmaxf(fmaf(acc[j][0], sc, sh), 0.f), 6.f);
            o.y = fminf(fmaxf(fmaf(acc[j][1], sc, sh), 0.f), 6.f);
            o.z = fminf(fmaxf(fmaf(acc[j][2], sc, sh), 0.f), 6.f);
            o.w = fminf(fmaxf(fmaf(acc[j][3], sc, sh), 0.f), 6.f);
            *reinterpret_cast<float4*>(ob + j * HW) = o;
        }
    }
}

extern "C" void kernel_launch(void* const* d_in, const int* in_sizes, int n_in,
                              void* d_out, int out_size) {
    const float* in    = (const float*)d_in[0];
    const float* w     = (const float*)d_in[1];
    const float* b     = (const float*)d_in[2];
    const float* gamma = (const float*)d_in[3];
    const float* beta  = (const float*)d_in[4];
    float* out = (float*)d_out;

    dim3 sgrid(CCH, NB);            // 6144 blocks, 224 threads
    stats_kernel<<<sgrid, 224>>>(in, w);

    // PDL: overlap successor launches with predecessor drain.
    cudaLaunchAttribute attrs[1];
    attrs[0].id = cudaLaunchAttributeProgrammaticStreamSerialization;
    attrs[0].val.programmaticStreamSerializationAllowed = 1;

    cudaLaunchConfig_t cfgF = {};
    cfgF.gridDim = dim3(CCH);       // 192 blocks, 1 warp each
    cfgF.blockDim = dim3(32);
    cfgF.attrs = attrs;
    cfgF.numAttrs = 1;
    cfgF.stream = 0;
    cudaLaunchKernelEx(&cfgF, finalize_kernel, b, gamma, beta);

    cudaLaunchConfig_t cfgO = {};
    cfgO.gridDim = dim3(TILES, CCH, NB);   // 43008 blocks
    cfgO.blockDim = dim3(128);
    cfgO.attrs = attrs;
    cfgO.numAttrs = 1;
    cfgO.stream = 0;
    cudaLaunchKernelEx(&cfgO, output_kernel, in, w, out);
}

// round 13
// speedup vs baseline: 1.0618x; 1.0197x over previous
#include <cuda_runtime.h>

#define NB   32
#define CCH  192
#define HW   112
#define IMG  (HW*HW)
#define TILE_H 16
#define TILES  (HW / TILE_H)   // 7
#define NHW_F  ((float)(NB*IMG))
#define BN_EPS 1e-5f

// Scratch (no cudaMalloc allowed): per-(c,n) partial sums (channel-major) + affine.
__device__ float g_p1[CCH * NB];   // sum of raw conv (no bias)
__device__ float g_p2[CCH * NB];   // sum of raw conv^2
__device__ float g_scale[CCH];
__device__ float g_shift[CCH];

// Load 6 input rows (h-1 .. h+4) as float4 per lane; lanes >=28 and OOB rows get 0.
__device__ __forceinline__ void load_rows(const float* __restrict__ base,
                                          int h, int lane, bool active,
                                          float4* v) {
    #pragma unroll
    for (int r = 0; r < 6; r++) {
        int row = h - 1 + r;
        float4 t = make_float4(0.f, 0.f, 0.f, 0.f);
        if (active && (unsigned)row < HW)
            t = __ldg(reinterpret_cast<const float4*>(base + row * HW) + lane);
        v[r] = t;
    }
}

// Scalar conv 4x4 micro-tile (proven fastest form).
// NOTE: lanes >= 28 produce garbage (their left halo shuffles in lane 27's real
// data) — callers MUST mask them out of any reduction/store.
__device__ __forceinline__ void conv44(const float4* v, const float* __restrict__ k,
                                       int lane, float acc[4][4]) {
    #pragma unroll
    for (int j = 0; j < 4; j++)
        #pragma unroll
        for (int i = 0; i < 4; i++)
            acc[j][i] = 0.f;

    #pragma unroll
    for (int r = 0; r < 6; r++) {
        float left  = __shfl_up_sync(0xFFFFFFFFu, v[r].w, 1);
        float right = __shfl_down_sync(0xFFFFFFFFu, v[r].x, 1);
        if (lane == 0) left = 0.f;
        float p[6] = { left, v[r].x, v[r].y, v[r].z, v[r].w, right };
        #pragma unroll
        for (int j = 0; j < 4; j++) {
            if (j >= r - 2 && j <= r) {
                const float k0 = k[3 * (r - j) + 0];
                const float k1 = k[3 * (r - j) + 1];
                const float k2 = k[3 * (r - j) + 2];
                #pragma unroll
                for (int i = 0; i < 4; i++)
                    acc[j][i] += k0 * p[i] + k1 * p[i + 1] + k2 * p[i + 2];
            }
        }
    }
}

// Pass 1 (proven, ~61us): per-(c,n) sums of conv and conv^2.
__global__ void __launch_bounds__(224)
stats_kernel(const float* __restrict__ in, const float* __restrict__ w) {
    __shared__ float red1[7], red2[7];
    int lane = threadIdx.x & 31, wid = threadIdx.x >> 5;
    int c = blockIdx.x, n = blockIdx.y;
    bool active = lane < 28;
    const float* base = in + (size_t)(n * CCH + c) * IMG;

    float k[9];
    #pragma unroll
    for (int i = 0; i < 9; i++) k[i] = __ldg(w + c * 9 + i);

    float s1 = 0.f, s2 = 0.f;
    #pragma unroll
    for (int chunk = 0; chunk < 4; chunk++) {
        int h = wid * TILE_H + chunk * 4;
        float4 v[6];
        load_rows(base, h, lane, active, v);
        float acc[4][4];
        conv44(v, k, lane, acc);
        if (active) {   // REQUIRED: lanes 28-31 hold garbage (see conv44 note)
            #pragma unroll
            for (int j = 0; j < 4; j++)
                #pragma unroll
                for (int i = 0; i < 4; i++) {
                    s1 += acc[j][i];
                    s2 += acc[j][i] * acc[j][i];
                }
        }
    }

    #pragma unroll
    for (int off = 16; off > 0; off >>= 1) {
        s1 += __shfl_down_sync(0xFFFFFFFFu, s1, off);
        s2 += __shfl_down_sync(0xFFFFFFFFu, s2, off);
    }
    if (lane == 0) { red1[wid] = s1; red2[wid] = s2; }
    __syncthreads();
    if (threadIdx.x == 0) {
        float t1 = 0.f, t2 = 0.f;
        #pragma unroll
        for (int i = 0; i < 7; i++) { t1 += red1[i]; t2 += red2[i]; }
        g_p1[c * NB + n] = t1;      // channel-major: finalize reads coalesced
        g_p2[c * NB + n] = t2;
    }
}

// Parallel finalize (proven): one warp per channel. PDL: launched while
// stats drains; sync before reading partials.
__global__ void finalize_kernel(const float* __restrict__ b,
                                const float* __restrict__ gamma,
                                const float* __restrict__ beta) {
    cudaGridDependencySynchronize();   // wait for stats partials
    int c = blockIdx.x;
    int lane = threadIdx.x;
    float p1 = g_p1[c * NB + lane];
    float p2 = g_p2[c * NB + lane];
    #pragma unroll
    for (int off = 16; off > 0; off >>= 1) {
        p1 += __shfl_down_sync(0xFFFFFFFFu, p1, off);
        p2 += __shfl_down_sync(0xFFFFFFFFu, p2, off);
    }
    if (lane == 0) {
        float bias  = __ldg(b + c);
        float sum_y = p1 + NHW_F * bias;
        float ssq_y = p2 + 2.f * bias * p1 + NHW_F * bias * bias;
        float mean  = sum_y / NHW_F;
        float var   = ssq_y / NHW_F - mean * mean;
        float sc    = __ldg(gamma + c) * rsqrtf(var + BN_EPS);
        g_scale[c] = sc;
        g_shift[c] = __ldg(beta + c) + sc * (bias - mean);
    }
}

// Pass 2: conv first (independent of finalize), then PDL sync, then folded
// scale/shift + ReLU6, plain float4 stores.
// Traversal REVERSED vs stats so the first output waves read the input region
// stats touched last (still L2-resident) -> fewer DRAM re-reads.
__global__ void __launch_bounds__(128)
output_kernel(const float* __restrict__ in,
              const float* __restrict__ w,
              float* __restrict__ out) {
    int lane = threadIdx.x & 31;
    int wid  = threadIdx.x >> 5;
    int c = (CCH - 1) - blockIdx.y;           // reversed
    int n = (NB  - 1) - blockIdx.z;           // reversed
    int h = ((TILES - 1) - blockIdx.x) * TILE_H + wid * 4;   // reversed tiles
    bool active = lane < 28;

    const float* base = in + (size_t)(n * CCH + c) * IMG;
    float k[9];
    #pragma unroll
    for (int i = 0; i < 9; i++) k[i] = __ldg(w + c * 9 + i);

    float4 v[6];
    load_rows(base, h, lane, active, v);

    float acc[4][4];
    conv44(v, k, lane, acc);

    cudaGridDependencySynchronize();   // finalize results ready past this point
    float sc = g_scale[c];
    float sh = g_shift[c];

    if (active) {
        float* ob = out + (size_t)(n * CCH + c) * IMG + h * HW + lane * 4;
        #pragma unroll
        for (int j = 0; j < 4; j++) {
            float4 o;
            o.x = fminf(fmaxf(fmaf(acc[j][0], sc, sh), 0.f), 6.f);
            o.y = fminf(fmaxf(fmaf(acc[j][1], sc, sh), 0.f), 6.f);
            o.z = fminf(fmaxf(fmaf(acc[j][2], sc, sh), 0.f), 6.f);
            o.w = fminf(fmaxf(fmaf(acc[j][3], sc, sh), 0.f), 6.f);
            *reinterpret_cast<float4*>(ob + j * HW) = o;
        }
    }
}

extern "C" void kernel_launch(void* const* d_in, const int* in_sizes, int n_in,
                              void* d_out, int out_size) {
    const float* in    = (const float*)d_in[0];
    const float* w     = (const float*)d_in[1];
    const float* b     = (const float*)d_in[2];
    const float* gamma = (const float*)d_in[3];
    const float* beta  = (const float*)d_in[4];
    float* out = (float*)d_out;

    dim3 sgrid(CCH, NB);            // 6144 blocks, 224 threads
    stats_kernel<<<sgrid, 224>>>(in, w);

    // PDL: overlap successor launches with predecessor drain.
    cudaLaunchAttribute attrs[1];
    attrs[0].id = cudaLaunchAttributeProgrammaticStreamSerialization;
    attrs[0].val.programmaticStreamSerializationAllowed = 1;

    cudaLaunchConfig_t cfgF = {};
    cfgF.gridDim = dim3(CCH);       // 192 blocks, 1 warp each
    cfgF.blockDim = dim3(32);
    cfgF.attrs = attrs;
    cfgF.numAttrs = 1;
    cfgF.stream = 0;
    cudaLaunchKernelEx(&cfgF, finalize_kernel, b, gamma, beta);

    cudaLaunchConfig_t cfgO = {};
    cfgO.gridDim = dim3(TILES, CCH, NB);   // 43008 blocks
    cfgO.blockDim = dim3(128);
    cfgO.attrs = attrs;
    cfgO.numAttrs = 1;
    cfgO.stream = 0;
    cudaLaunchKernelEx(&cfgO, output_kernel, in, w, out);
}